// round 1
// baseline (speedup 1.0000x reference)
#include <cuda_runtime.h>
#include <math.h>

#define BTOT 32768
#define NDM 256
#define NDI 256
#define NDS 16
#define NFF 512

// ---- scratch (static device globals; no allocation) ----
__device__ float g_pos[(size_t)BTOT*NDM];
__device__ float g_u[(size_t)BTOT*NDI];
__device__ float g_gate[(size_t)BTOT*NDI];
__device__ float g_delta[(size_t)BTOT*NDI];
__device__ float g_Bm[(size_t)BTOT*NDS];
__device__ float g_Cm[(size_t)BTOT*NDS];
__device__ float g_y[(size_t)BTOT*NDI];
__device__ float g_t[(size_t)BTOT*NFF];
__device__ float g_s[(size_t)BTOT*NDM];

__device__ __forceinline__ float siluf(float x) { return x / (1.f + expf(-x)); }

// ---------------- K1: sine embedding ----------------
// pos[b, a*64 + 2j]   = sin(x0[b,a]*2pi / 10000^(j/32))
// pos[b, a*64 + 2j+1] = cos(x0[b,a]*2pi / 10000^(j/32))
__global__ void __launch_bounds__(256) k_embed(const float* __restrict__ x0) {
    int idx = blockIdx.x * 256 + threadIdx.x;        // over BTOT*256
    int b = idx >> 8;
    int c = idx & 255;
    int a = c >> 6;
    int w = c & 63;
    int j = w >> 1;
    float v = x0[b * 4 + a];
    float freq_inv = expf(-(float)j * 0.28782313662425576f); // ln(10000)/32
    float p = v * 6.283185307179586f * freq_inv;
    g_pos[idx] = (w & 1) ? cosf(p) : sinf(p);
}

// ---------------- tiled fp32 SGEMM: C[m,n] = sum_k A[m,k]*W[n,k] ----------------
// MODE 0: A=g_pos K=256, N=512: n<256 -> g_u = silu(v); else g_gate = v
// MODE 1: A=g_y   K=256, N=512: g_t = relu(v + b1[n])
// MODE 2: A=g_t   K=512, N=256: g_s = v + b2[n] + g_y[m,n]
template <int K, int MODE>
__global__ void __launch_bounds__(256) k_sgemm(const float* __restrict__ W,
                                               const float* __restrict__ bias) {
    __shared__ float As[16][128];
    __shared__ float Ws[16][128];
    const float* __restrict__ A = (MODE == 0) ? g_pos : (MODE == 1 ? g_y : g_t);
    const int tid = threadIdx.x;
    const int tx = tid & 15;
    const int ty = tid >> 4;
    const int m0 = blockIdx.y * 128;
    const int n0 = blockIdx.x * 128;

    float acc[8][8];
#pragma unroll
    for (int i = 0; i < 8; i++)
#pragma unroll
        for (int j = 0; j < 8; j++) acc[i][j] = 0.f;

    for (int k0 = 0; k0 < K; k0 += 16) {
#pragma unroll
        for (int i = 0; i < 2; i++) {
            int f = tid * 2 + i;            // 0..511
            int row = f >> 2;               // 0..127
            int kc = (f & 3) << 2;          // 0,4,8,12
            float4 av = *(const float4*)(A + (size_t)(m0 + row) * K + k0 + kc);
            As[kc + 0][row] = av.x; As[kc + 1][row] = av.y;
            As[kc + 2][row] = av.z; As[kc + 3][row] = av.w;
            float4 wv = *(const float4*)(W + (size_t)(n0 + row) * K + k0 + kc);
            Ws[kc + 0][row] = wv.x; Ws[kc + 1][row] = wv.y;
            Ws[kc + 2][row] = wv.z; Ws[kc + 3][row] = wv.w;
        }
        __syncthreads();
#pragma unroll
        for (int kk = 0; kk < 16; kk++) {
            float a[8], bb[8];
            *(float4*)&a[0] = *(const float4*)&As[kk][ty * 8];
            *(float4*)&a[4] = *(const float4*)&As[kk][ty * 8 + 4];
            *(float4*)&bb[0] = *(const float4*)&Ws[kk][tx * 8];
            *(float4*)&bb[4] = *(const float4*)&Ws[kk][tx * 8 + 4];
#pragma unroll
            for (int i = 0; i < 8; i++)
#pragma unroll
                for (int j = 0; j < 8; j++) acc[i][j] = fmaf(a[i], bb[j], acc[i][j]);
        }
        __syncthreads();
    }

#pragma unroll
    for (int i = 0; i < 8; i++) {
        int m = m0 + ty * 8 + i;
#pragma unroll
        for (int j = 0; j < 8; j++) {
            int n = n0 + tx * 8 + j;
            float v = acc[i][j];
            if (MODE == 0) {
                if (n < 256) g_u[(size_t)m * 256 + n] = siluf(v);
                else         g_gate[(size_t)m * 256 + n - 256] = v;
            } else if (MODE == 1) {
                v += bias[n];
                g_t[(size_t)m * 512 + n] = fmaxf(v, 0.f);
            } else {
                v += bias[n] + g_y[(size_t)m * 256 + n];
                g_s[(size_t)m * 256 + n] = v;
            }
        }
    }
}

// ---------------- K3: x_dbl = flow @ W_x^T (48 cols), then delta = softplus(dlt @ W_dt^T + b_dt)
__global__ void __launch_bounds__(256) k_xdbl(const float* __restrict__ flow,
                                              const float* __restrict__ W_x,
                                              const float* __restrict__ W_dt,
                                              const float* __restrict__ b_dt) {
    __shared__ float sF[16 * 256];
    __shared__ float sdlt[16 * 16];
    int b0 = blockIdx.x * 16;
    int tid = threadIdx.x;

    for (int i = tid; i < 16 * 64; i += 256)
        ((float4*)sF)[i] = ((const float4*)flow)[(size_t)b0 * 64 + i];
    __syncthreads();

    for (int o = tid; o < 768; o += 256) {  // 16 rows x 48 cols
        int row = o / 48;
        int col = o - row * 48;
        const float4* wr = (const float4*)(W_x + col * 256);
        const float4* fr = (const float4*)(sF + row * 256);
        float s = 0.f;
#pragma unroll 8
        for (int k = 0; k < 64; k++) {
            float4 w = __ldg(&wr[k]);
            float4 f = fr[k];
            s += w.x * f.x + w.y * f.y + w.z * f.z + w.w * f.w;
        }
        int b = b0 + row;
        if (col < 16)       sdlt[row * 16 + col] = s;
        else if (col < 32)  g_Bm[(size_t)b * 16 + col - 16] = s;
        else                g_Cm[(size_t)b * 16 + col - 32] = s;
    }
    __syncthreads();

    // delta: each thread owns channel d = tid, loops over 16 rows
    int d = tid;
    float4 wd0 = __ldg((const float4*)(W_dt + d * 16));
    float4 wd1 = __ldg((const float4*)(W_dt + d * 16 + 4));
    float4 wd2 = __ldg((const float4*)(W_dt + d * 16 + 8));
    float4 wd3 = __ldg((const float4*)(W_dt + d * 16 + 12));
    float bd = __ldg(&b_dt[d]);
#pragma unroll 4
    for (int row = 0; row < 16; row++) {
        const float* dl = sdlt + row * 16;
        float s = bd;
        s += wd0.x * dl[0]  + wd0.y * dl[1]  + wd0.z * dl[2]  + wd0.w * dl[3];
        s += wd1.x * dl[4]  + wd1.y * dl[5]  + wd1.z * dl[6]  + wd1.w * dl[7];
        s += wd2.x * dl[8]  + wd2.y * dl[9]  + wd2.z * dl[10] + wd2.w * dl[11];
        s += wd3.x * dl[12] + wd3.y * dl[13] + wd3.z * dl[14] + wd3.w * dl[15];
        g_delta[(size_t)(b0 + row) * 256 + d] = log1pf(expf(s));
    }
}

// ---------------- K4: SSM state update; one block per row, thread = channel d ----------------
__global__ void __launch_bounds__(256) k_mamba(const float* __restrict__ h,
                                               const float* __restrict__ A_log,
                                               const float* __restrict__ Dv,
                                               float* __restrict__ h_new) {
    int b = blockIdx.x;
    int d = threadIdx.x;
    __shared__ float sB[16], sC[16];
    if (d < 16)       sB[d] = g_Bm[(size_t)b * 16 + d];
    else if (d < 32)  sC[d - 16] = g_Cm[(size_t)b * 16 + d - 16];
    __syncthreads();

    size_t base = (size_t)b * 256 + d;
    float delta = g_delta[base];
    float u = g_u[base];
    float du = delta * u;
    const float4* hp = (const float4*)(h + base * 16);
    float4* op = (float4*)(h_new + base * 16);
    const float4* ap = (const float4*)(A_log + d * 16);
    float y = 0.f;
#pragma unroll
    for (int q = 0; q < 4; q++) {
        float4 hv = hp[q];
        float4 al = __ldg(&ap[q]);
        float4 o;
        o.x = expf(-expf(al.x) * delta) * hv.x + du * sB[q * 4 + 0];
        o.y = expf(-expf(al.y) * delta) * hv.y + du * sB[q * 4 + 1];
        o.z = expf(-expf(al.z) * delta) * hv.z + du * sB[q * 4 + 2];
        o.w = expf(-expf(al.w) * delta) * hv.w + du * sB[q * 4 + 3];
        op[q] = o;
        y += o.x * sC[q * 4 + 0] + o.y * sC[q * 4 + 1]
           + o.z * sC[q * 4 + 2] + o.w * sC[q * 4 + 3];
    }
    y += u * __ldg(&Dv[d]);
    float g = g_gate[base];
    g_y[base] = y * siluf(g);
}

// ---------------- K7: LayerNorm + 4-way head + sigmoid; warp per row ----------------
__global__ void __launch_bounds__(256) k_head(const float* __restrict__ gamma,
                                              const float* __restrict__ beta,
                                              const float* __restrict__ W_bb,
                                              const float* __restrict__ b_bb,
                                              float* __restrict__ out) {
    int warp = threadIdx.x >> 5;
    int lane = threadIdx.x & 31;
    int b = blockIdx.x * 8 + warp;
    const float* srow = g_s + (size_t)b * 256;

    float v[8];
    float sum = 0.f;
#pragma unroll
    for (int i = 0; i < 8; i++) { v[i] = srow[i * 32 + lane]; sum += v[i]; }
#pragma unroll
    for (int o = 16; o > 0; o >>= 1) sum += __shfl_xor_sync(0xffffffffu, sum, o);
    float mu = sum * (1.f / 256.f);
    float sq = 0.f;
#pragma unroll
    for (int i = 0; i < 8; i++) { float dd = v[i] - mu; sq += dd * dd; }
#pragma unroll
    for (int o = 16; o > 0; o >>= 1) sq += __shfl_xor_sync(0xffffffffu, sq, o);
    float inv = rsqrtf(sq * (1.f / 256.f) + 1e-5f);

    float a0 = 0.f, a1 = 0.f, a2 = 0.f, a3 = 0.f;
#pragma unroll
    for (int i = 0; i < 8; i++) {
        int c = i * 32 + lane;
        float sn = (v[i] - mu) * inv * __ldg(&gamma[c]) + __ldg(&beta[c]);
        a0 += sn * __ldg(&W_bb[c]);
        a1 += sn * __ldg(&W_bb[256 + c]);
        a2 += sn * __ldg(&W_bb[512 + c]);
        a3 += sn * __ldg(&W_bb[768 + c]);
    }
#pragma unroll
    for (int o = 16; o > 0; o >>= 1) {
        a0 += __shfl_xor_sync(0xffffffffu, a0, o);
        a1 += __shfl_xor_sync(0xffffffffu, a1, o);
        a2 += __shfl_xor_sync(0xffffffffu, a2, o);
        a3 += __shfl_xor_sync(0xffffffffu, a3, o);
    }
    if (lane == 0) {
        out[b * 4 + 0] = 1.f / (1.f + expf(-(a0 + __ldg(&b_bb[0]))));
        out[b * 4 + 1] = 1.f / (1.f + expf(-(a1 + __ldg(&b_bb[1]))));
        out[b * 4 + 2] = 1.f / (1.f + expf(-(a2 + __ldg(&b_bb[2]))));
        out[b * 4 + 3] = 1.f / (1.f + expf(-(a3 + __ldg(&b_bb[3]))));
    }
}

extern "C" void kernel_launch(void* const* d_in, const int* in_sizes, int n_in,
                              void* d_out, int out_size) {
    const float* x0    = (const float*)d_in[0];
    const float* flow  = (const float*)d_in[1];
    const float* h     = (const float*)d_in[2];
    const float* W_in  = (const float*)d_in[3];
    const float* W_x   = (const float*)d_in[4];
    const float* W_dt  = (const float*)d_in[5];
    const float* b_dt  = (const float*)d_in[6];
    const float* A_log = (const float*)d_in[7];
    const float* Dv    = (const float*)d_in[8];
    const float* W1    = (const float*)d_in[9];
    const float* b1    = (const float*)d_in[10];
    const float* W2    = (const float*)d_in[11];
    const float* b2    = (const float*)d_in[12];
    const float* gamma = (const float*)d_in[13];
    const float* beta  = (const float*)d_in[14];
    const float* W_bb  = (const float*)d_in[15];
    const float* b_bb  = (const float*)d_in[16];

    float* out   = (float*)d_out;                 // (B, 4)
    float* h_new = out + (size_t)BTOT * 4;        // (B, 256, 16)

    k_embed<<<BTOT, 256>>>(x0);
    k_sgemm<256, 0><<<dim3(4, BTOT / 128), 256>>>(W_in, (const float*)nullptr);
    k_xdbl<<<BTOT / 16, 256>>>(flow, W_x, W_dt, b_dt);
    k_mamba<<<BTOT, 256>>>(h, A_log, Dv, h_new);
    k_sgemm<256, 1><<<dim3(4, BTOT / 128), 256>>>(W1, b1);
    k_sgemm<512, 2><<<dim3(2, BTOT / 128), 256>>>(W2, b2);
    k_head<<<BTOT / 8, 256>>>(gamma, beta, W_bb, b_bb, out);
}

// round 2
// speedup vs baseline: 1.0049x; 1.0049x over previous
#include <cuda_runtime.h>
#include <math.h>

#define BTOT 32768
#define NDM 256
#define NDI 256
#define NDS 16
#define NFF 512

// ---- scratch (static device globals; no allocation) ----
__device__ float g_pos[(size_t)BTOT*NDM];
__device__ float g_u[(size_t)BTOT*NDI];
__device__ float g_gate[(size_t)BTOT*NDI];
__device__ float g_delta[(size_t)BTOT*NDI];
__device__ float g_Bm[(size_t)BTOT*NDS];
__device__ float g_Cm[(size_t)BTOT*NDS];
__device__ float g_y[(size_t)BTOT*NDI];
__device__ float g_t[(size_t)BTOT*NFF];
__device__ float g_s[(size_t)BTOT*NDM];
__device__ float g_negA[NDI*NDS];

__device__ __forceinline__ float siluf(float x) { return x / (1.f + __expf(-x)); }

__device__ __forceinline__ unsigned long long fma2(unsigned long long a,
                                                   unsigned long long b,
                                                   unsigned long long c) {
    unsigned long long d;
    asm("fma.rn.f32x2 %0, %1, %2, %3;" : "=l"(d) : "l"(a), "l"(b), "l"(c));
    return d;
}
__device__ __forceinline__ unsigned long long dup2(float x) {
    unsigned long long p;
    asm("mov.b64 %0, {%1, %2};" : "=l"(p) : "f"(x), "f"(x));
    return p;
}
__device__ __forceinline__ float lo32(unsigned long long v) {
    return __uint_as_float((unsigned)v);
}
__device__ __forceinline__ float hi32(unsigned long long v) {
    return __uint_as_float((unsigned)(v >> 32));
}

// ---------------- K0: precompute -exp(A_log) ----------------
__global__ void k_prep(const float* __restrict__ A_log) {
    int i = blockIdx.x * 256 + threadIdx.x;
    g_negA[i] = -expf(A_log[i]);
}

// ---------------- K1: sine embedding ----------------
__global__ void __launch_bounds__(256) k_embed(const float* __restrict__ x0) {
    int idx = blockIdx.x * 256 + threadIdx.x;        // over BTOT*256
    int b = idx >> 8;
    int c = idx & 255;
    int a = c >> 6;
    int w = c & 63;
    int j = w >> 1;
    float v = x0[b * 4 + a];
    float freq_inv = __expf(-(float)j * 0.28782313662425576f); // ln(10000)/32
    float p = v * 6.283185307179586f * freq_inv;
    g_pos[idx] = (w & 1) ? __cosf(p) : __sinf(p);
}

// ---------------- tiled fp32 SGEMM with packed f32x2 FMA ----------------
// C[m,n] = sum_k A[m,k]*W[n,k]
// MODE 0: A=g_pos K=256, N=512: n<256 -> g_u = silu(v); else g_gate = v
// MODE 1: A=g_y   K=256, N=512: g_t = relu(v + b1[n])
// MODE 2: A=g_t   K=512, N=256: g_s = v + b2[n] + g_y[m,n]
template <int K, int MODE>
__global__ void __launch_bounds__(256) k_sgemm(const float* __restrict__ W,
                                               const float* __restrict__ bias) {
    __shared__ float As[16][128];
    __shared__ float Ws[16][128];
    const float* __restrict__ A = (MODE == 0) ? g_pos : (MODE == 1 ? g_y : g_t);
    const int tid = threadIdx.x;
    const int tx = tid & 15;
    const int ty = tid >> 4;
    const int m0 = blockIdx.y * 128;
    const int n0 = blockIdx.x * 128;

    unsigned long long acc2[8][4];
#pragma unroll
    for (int i = 0; i < 8; i++)
#pragma unroll
        for (int j = 0; j < 4; j++) acc2[i][j] = 0ull;

    for (int k0 = 0; k0 < K; k0 += 16) {
#pragma unroll
        for (int i = 0; i < 2; i++) {
            int f = tid * 2 + i;            // 0..511
            int row = f >> 2;               // 0..127
            int kc = (f & 3) << 2;          // 0,4,8,12
            float4 av = *(const float4*)(A + (size_t)(m0 + row) * K + k0 + kc);
            As[kc + 0][row] = av.x; As[kc + 1][row] = av.y;
            As[kc + 2][row] = av.z; As[kc + 3][row] = av.w;
            float4 wv = *(const float4*)(W + (size_t)(n0 + row) * K + k0 + kc);
            Ws[kc + 0][row] = wv.x; Ws[kc + 1][row] = wv.y;
            Ws[kc + 2][row] = wv.z; Ws[kc + 3][row] = wv.w;
        }
        __syncthreads();
#pragma unroll
        for (int kk = 0; kk < 16; kk++) {
            float a[8];
            *(float4*)&a[0] = *(const float4*)&As[kk][ty * 8];
            *(float4*)&a[4] = *(const float4*)&As[kk][ty * 8 + 4];
            const unsigned long long* wq =
                (const unsigned long long*)&Ws[kk][tx * 8];
            unsigned long long b0 = wq[0], b1 = wq[1], b2 = wq[2], b3 = wq[3];
#pragma unroll
            for (int i = 0; i < 8; i++) {
                unsigned long long ap = dup2(a[i]);
                acc2[i][0] = fma2(ap, b0, acc2[i][0]);
                acc2[i][1] = fma2(ap, b1, acc2[i][1]);
                acc2[i][2] = fma2(ap, b2, acc2[i][2]);
                acc2[i][3] = fma2(ap, b3, acc2[i][3]);
            }
        }
        __syncthreads();
    }

#pragma unroll
    for (int i = 0; i < 8; i++) {
        int m = m0 + ty * 8 + i;
#pragma unroll
        for (int j2 = 0; j2 < 4; j2++) {
#pragma unroll
            for (int half = 0; half < 2; half++) {
                int n = n0 + tx * 8 + j2 * 2 + half;
                float v = half ? hi32(acc2[i][j2]) : lo32(acc2[i][j2]);
                if (MODE == 0) {
                    if (n < 256) g_u[(size_t)m * 256 + n] = siluf(v);
                    else         g_gate[(size_t)m * 256 + n - 256] = v;
                } else if (MODE == 1) {
                    v += bias[n];
                    g_t[(size_t)m * 512 + n] = fmaxf(v, 0.f);
                } else {
                    v += bias[n] + g_y[(size_t)m * 256 + n];
                    g_s[(size_t)m * 256 + n] = v;
                }
            }
        }
    }
}

// ---------------- K3: x_dbl = flow @ W_x^T (48 cols), then delta = softplus(dlt @ W_dt^T + b_dt)
__global__ void __launch_bounds__(256) k_xdbl(const float* __restrict__ flow,
                                              const float* __restrict__ W_x,
                                              const float* __restrict__ W_dt,
                                              const float* __restrict__ b_dt) {
    __shared__ float sF[16 * 256];
    __shared__ float sdlt[16 * 16];
    int b0 = blockIdx.x * 16;
    int tid = threadIdx.x;

    for (int i = tid; i < 16 * 64; i += 256)
        ((float4*)sF)[i] = ((const float4*)flow)[(size_t)b0 * 64 + i];
    __syncthreads();

    for (int o = tid; o < 768; o += 256) {  // 16 rows x 48 cols
        int row = o / 48;
        int col = o - row * 48;
        const float4* wr = (const float4*)(W_x + col * 256);
        const float4* fr = (const float4*)(sF + row * 256);
        float s = 0.f;
#pragma unroll 8
        for (int k = 0; k < 64; k++) {
            float4 w = __ldg(&wr[k]);
            float4 f = fr[k];
            s += w.x * f.x + w.y * f.y + w.z * f.z + w.w * f.w;
        }
        int b = b0 + row;
        if (col < 16)       sdlt[row * 16 + col] = s;
        else if (col < 32)  g_Bm[(size_t)b * 16 + col - 16] = s;
        else                g_Cm[(size_t)b * 16 + col - 32] = s;
    }
    __syncthreads();

    int d = tid;
    float4 wd0 = __ldg((const float4*)(W_dt + d * 16));
    float4 wd1 = __ldg((const float4*)(W_dt + d * 16 + 4));
    float4 wd2 = __ldg((const float4*)(W_dt + d * 16 + 8));
    float4 wd3 = __ldg((const float4*)(W_dt + d * 16 + 12));
    float bd = __ldg(&b_dt[d]);
#pragma unroll 4
    for (int row = 0; row < 16; row++) {
        const float* dl = sdlt + row * 16;
        float s = bd;
        s += wd0.x * dl[0]  + wd0.y * dl[1]  + wd0.z * dl[2]  + wd0.w * dl[3];
        s += wd1.x * dl[4]  + wd1.y * dl[5]  + wd1.z * dl[6]  + wd1.w * dl[7];
        s += wd2.x * dl[8]  + wd2.y * dl[9]  + wd2.z * dl[10] + wd2.w * dl[11];
        s += wd3.x * dl[12] + wd3.y * dl[13] + wd3.z * dl[14] + wd3.w * dl[15];
        g_delta[(size_t)(b0 + row) * 256 + d] = log1pf(expf(s));
    }
}

// ---------------- K4: SSM state update; one block per row, thread = channel d ----------------
__global__ void __launch_bounds__(256) k_mamba(const float* __restrict__ h,
                                               const float* __restrict__ Dv,
                                               float* __restrict__ h_new) {
    int b = blockIdx.x;
    int d = threadIdx.x;
    __shared__ float sB[16], sC[16];
    if (d < 16)       sB[d] = g_Bm[(size_t)b * 16 + d];
    else if (d < 32)  sC[d - 16] = g_Cm[(size_t)b * 16 + d - 16];
    __syncthreads();

    size_t base = (size_t)b * 256 + d;
    float delta = g_delta[base];
    float u = g_u[base];
    float du = delta * u;
    const float4* hp = (const float4*)(h + base * 16);
    float4* op = (float4*)(h_new + base * 16);
    const float4* ap = (const float4*)(g_negA + d * 16);
    float y = 0.f;
#pragma unroll
    for (int q = 0; q < 4; q++) {
        float4 hv = __ldcs(&hp[q]);
        float4 al = __ldg(&ap[q]);
        float4 o;
        o.x = __expf(al.x * delta) * hv.x + du * sB[q * 4 + 0];
        o.y = __expf(al.y * delta) * hv.y + du * sB[q * 4 + 1];
        o.z = __expf(al.z * delta) * hv.z + du * sB[q * 4 + 2];
        o.w = __expf(al.w * delta) * hv.w + du * sB[q * 4 + 3];
        __stcs(&op[q], o);
        y += o.x * sC[q * 4 + 0] + o.y * sC[q * 4 + 1]
           + o.z * sC[q * 4 + 2] + o.w * sC[q * 4 + 3];
    }
    y += u * __ldg(&Dv[d]);
    float g = g_gate[base];
    g_y[base] = y * siluf(g);
}

// ---------------- K7: LayerNorm + 4-way head + sigmoid; warp per row ----------------
__global__ void __launch_bounds__(256) k_head(const float* __restrict__ gamma,
                                              const float* __restrict__ beta,
                                              const float* __restrict__ W_bb,
                                              const float* __restrict__ b_bb,
                                              float* __restrict__ out) {
    int warp = threadIdx.x >> 5;
    int lane = threadIdx.x & 31;
    int b = blockIdx.x * 8 + warp;
    const float* srow = g_s + (size_t)b * 256;

    float v[8];
    float sum = 0.f;
#pragma unroll
    for (int i = 0; i < 8; i++) { v[i] = srow[i * 32 + lane]; sum += v[i]; }
#pragma unroll
    for (int o = 16; o > 0; o >>= 1) sum += __shfl_xor_sync(0xffffffffu, sum, o);
    float mu = sum * (1.f / 256.f);
    float sq = 0.f;
#pragma unroll
    for (int i = 0; i < 8; i++) { float dd = v[i] - mu; sq += dd * dd; }
#pragma unroll
    for (int o = 16; o > 0; o >>= 1) sq += __shfl_xor_sync(0xffffffffu, sq, o);
    float inv = rsqrtf(sq * (1.f / 256.f) + 1e-5f);

    float a0 = 0.f, a1 = 0.f, a2 = 0.f, a3 = 0.f;
#pragma unroll
    for (int i = 0; i < 8; i++) {
        int c = i * 32 + lane;
        float sn = (v[i] - mu) * inv * __ldg(&gamma[c]) + __ldg(&beta[c]);
        a0 += sn * __ldg(&W_bb[c]);
        a1 += sn * __ldg(&W_bb[256 + c]);
        a2 += sn * __ldg(&W_bb[512 + c]);
        a3 += sn * __ldg(&W_bb[768 + c]);
    }
#pragma unroll
    for (int o = 16; o > 0; o >>= 1) {
        a0 += __shfl_xor_sync(0xffffffffu, a0, o);
        a1 += __shfl_xor_sync(0xffffffffu, a1, o);
        a2 += __shfl_xor_sync(0xffffffffu, a2, o);
        a3 += __shfl_xor_sync(0xffffffffu, a3, o);
    }
    if (lane == 0) {
        out[b * 4 + 0] = 1.f / (1.f + expf(-(a0 + __ldg(&b_bb[0]))));
        out[b * 4 + 1] = 1.f / (1.f + expf(-(a1 + __ldg(&b_bb[1]))));
        out[b * 4 + 2] = 1.f / (1.f + expf(-(a2 + __ldg(&b_bb[2]))));
        out[b * 4 + 3] = 1.f / (1.f + expf(-(a3 + __ldg(&b_bb[3]))));
    }
}

extern "C" void kernel_launch(void* const* d_in, const int* in_sizes, int n_in,
                              void* d_out, int out_size) {
    const float* x0    = (const float*)d_in[0];
    const float* flow  = (const float*)d_in[1];
    const float* h     = (const float*)d_in[2];
    const float* W_in  = (const float*)d_in[3];
    const float* W_x   = (const float*)d_in[4];
    const float* W_dt  = (const float*)d_in[5];
    const float* b_dt  = (const float*)d_in[6];
    const float* A_log = (const float*)d_in[7];
    const float* Dv    = (const float*)d_in[8];
    const float* W1    = (const float*)d_in[9];
    const float* b1    = (const float*)d_in[10];
    const float* W2    = (const float*)d_in[11];
    const float* b2    = (const float*)d_in[12];
    const float* gamma = (const float*)d_in[13];
    const float* beta  = (const float*)d_in[14];
    const float* W_bb  = (const float*)d_in[15];
    const float* b_bb  = (const float*)d_in[16];

    float* out   = (float*)d_out;                 // (B, 4)
    float* h_new = out + (size_t)BTOT * 4;        // (B, 256, 16)

    k_prep<<<16, 256>>>(A_log);
    k_embed<<<BTOT, 256>>>(x0);
    k_sgemm<256, 0><<<dim3(4, BTOT / 128), 256>>>(W_in, (const float*)nullptr);
    k_xdbl<<<BTOT / 16, 256>>>(flow, W_x, W_dt, b_dt);
    k_mamba<<<BTOT, 256>>>(h, Dv, h_new);
    k_sgemm<256, 1><<<dim3(4, BTOT / 128), 256>>>(W1, b1);
    k_sgemm<512, 2><<<dim3(2, BTOT / 128), 256>>>(W2, b2);
    k_head<<<BTOT / 8, 256>>>(gamma, beta, W_bb, b_bb, out);
}

// round 3
// speedup vs baseline: 1.2016x; 1.1958x over previous
#include <cuda_runtime.h>
#include <math.h>

#define BTOT 32768
#define NDM 256
#define NDI 256
#define NDS 16
#define NFF 512

// ---- scratch (static device globals; no allocation) ----
__device__ float g_pos[(size_t)BTOT*NDM];
__device__ float g_u[(size_t)BTOT*NDI];
__device__ float g_gate[(size_t)BTOT*NDI];
__device__ float g_delta[(size_t)BTOT*NDI];
__device__ float g_Bm[(size_t)BTOT*NDS];
__device__ float g_Cm[(size_t)BTOT*NDS];
__device__ float g_y[(size_t)BTOT*NDI];
__device__ float g_t[(size_t)BTOT*NFF];
__device__ float g_s[(size_t)BTOT*NDM];
__device__ float g_negA[NDI*NDS];

__device__ __forceinline__ float siluf(float x) { return x / (1.f + __expf(-x)); }

__device__ __forceinline__ unsigned long long fma2(unsigned long long a,
                                                   unsigned long long b,
                                                   unsigned long long c) {
    unsigned long long d;
    asm("fma.rn.f32x2 %0, %1, %2, %3;" : "=l"(d) : "l"(a), "l"(b), "l"(c));
    return d;
}
__device__ __forceinline__ unsigned long long dup2(float x) {
    unsigned long long p;
    asm("mov.b64 %0, {%1, %2};" : "=l"(p) : "f"(x), "f"(x));
    return p;
}
__device__ __forceinline__ float lo32(unsigned long long v) {
    return __uint_as_float((unsigned)v);
}
__device__ __forceinline__ float hi32(unsigned long long v) {
    return __uint_as_float((unsigned)(v >> 32));
}

// ---------------- K0: precompute -exp(A_log) ----------------
__global__ void k_prep(const float* __restrict__ A_log) {
    int i = blockIdx.x * 256 + threadIdx.x;
    g_negA[i] = -expf(A_log[i]);
}

// ---------------- K1: sine embedding ----------------
__global__ void __launch_bounds__(256) k_embed(const float* __restrict__ x0) {
    int idx = blockIdx.x * 256 + threadIdx.x;        // over BTOT*256
    int b = idx >> 8;
    int c = idx & 255;
    int a = c >> 6;
    int w = c & 63;
    int j = w >> 1;
    float v = x0[b * 4 + a];
    float freq_inv = __expf(-(float)j * 0.28782313662425576f); // ln(10000)/32
    float p = v * 6.283185307179586f * freq_inv;
    g_pos[idx] = (w & 1) ? __cosf(p) : __sinf(p);
}

// ---------------- tiled fp32 SGEMM with packed f32x2 FMA ----------------
// C[m,n] = sum_k A[m,k]*W[n,k]
// MODE 0: A=g_pos K=256, N=512: n<256 -> g_u = silu(v); else g_gate = v
// MODE 1: A=g_y   K=256, N=512: g_t = relu(v + b1[n])
// MODE 2: A=g_t   K=512, N=256: g_s = v + b2[n] + g_y[m,n]
template <int K, int MODE>
__global__ void __launch_bounds__(256) k_sgemm(const float* __restrict__ W,
                                               const float* __restrict__ bias) {
    __shared__ float As[16][128];
    __shared__ float Ws[16][128];
    const float* __restrict__ A = (MODE == 0) ? g_pos : (MODE == 1 ? g_y : g_t);
    const int tid = threadIdx.x;
    const int tx = tid & 15;
    const int ty = tid >> 4;
    const int m0 = blockIdx.y * 128;
    const int n0 = blockIdx.x * 128;

    unsigned long long acc2[8][4];
#pragma unroll
    for (int i = 0; i < 8; i++)
#pragma unroll
        for (int j = 0; j < 4; j++) acc2[i][j] = 0ull;

    for (int k0 = 0; k0 < K; k0 += 16) {
#pragma unroll
        for (int i = 0; i < 2; i++) {
            int f = tid * 2 + i;            // 0..511
            int row = f >> 2;               // 0..127
            int kc = (f & 3) << 2;          // 0,4,8,12
            float4 av = *(const float4*)(A + (size_t)(m0 + row) * K + k0 + kc);
            As[kc + 0][row] = av.x; As[kc + 1][row] = av.y;
            As[kc + 2][row] = av.z; As[kc + 3][row] = av.w;
            float4 wv = *(const float4*)(W + (size_t)(n0 + row) * K + k0 + kc);
            Ws[kc + 0][row] = wv.x; Ws[kc + 1][row] = wv.y;
            Ws[kc + 2][row] = wv.z; Ws[kc + 3][row] = wv.w;
        }
        __syncthreads();
#pragma unroll
        for (int kk = 0; kk < 16; kk++) {
            float a[8];
            *(float4*)&a[0] = *(const float4*)&As[kk][ty * 8];
            *(float4*)&a[4] = *(const float4*)&As[kk][ty * 8 + 4];
            const unsigned long long* wq =
                (const unsigned long long*)&Ws[kk][tx * 8];
            unsigned long long b0 = wq[0], b1 = wq[1], b2 = wq[2], b3 = wq[3];
#pragma unroll
            for (int i = 0; i < 8; i++) {
                unsigned long long ap = dup2(a[i]);
                acc2[i][0] = fma2(ap, b0, acc2[i][0]);
                acc2[i][1] = fma2(ap, b1, acc2[i][1]);
                acc2[i][2] = fma2(ap, b2, acc2[i][2]);
                acc2[i][3] = fma2(ap, b3, acc2[i][3]);
            }
        }
        __syncthreads();
    }

#pragma unroll
    for (int i = 0; i < 8; i++) {
        int m = m0 + ty * 8 + i;
#pragma unroll
        for (int j2 = 0; j2 < 4; j2++) {
#pragma unroll
            for (int half = 0; half < 2; half++) {
                int n = n0 + tx * 8 + j2 * 2 + half;
                float v = half ? hi32(acc2[i][j2]) : lo32(acc2[i][j2]);
                if (MODE == 0) {
                    if (n < 256) g_u[(size_t)m * 256 + n] = siluf(v);
                    else         g_gate[(size_t)m * 256 + n - 256] = v;
                } else if (MODE == 1) {
                    v += bias[n];
                    g_t[(size_t)m * 512 + n] = fmaxf(v, 0.f);
                } else {
                    v += bias[n] + g_y[(size_t)m * 256 + n];
                    g_s[(size_t)m * 256 + n] = v;
                }
            }
        }
    }
}

// ---------------- K3: x_dbl = flow @ W_x^T, col-split across blockIdx.y ----------------
// blockIdx.y = 0: cols 0..15  -> dlt -> delta = softplus(dlt @ W_dt^T + b_dt)
// blockIdx.y = 1: cols 16..31 -> g_Bm
// blockIdx.y = 2: cols 32..47 -> g_Cm
__global__ void __launch_bounds__(256) k_xdbl(const float* __restrict__ flow,
                                              const float* __restrict__ W_x,
                                              const float* __restrict__ W_dt,
                                              const float* __restrict__ b_dt) {
    __shared__ float sW[16][260];   // 16 cols x 256 k, padded stride 260
    __shared__ float sF[16][260];   // 16 rows x 256 k
    __shared__ float sdlt[16][17];
    const int b0 = blockIdx.x * 16;
    const int cb = blockIdx.y;      // col block
    const int tid = threadIdx.x;

    // Stage W_x[cb*16 .. cb*16+15][0..255] and flow rows into smem (float4 coalesced)
#pragma unroll
    for (int i = 0; i < 4; i++) {
        int f = tid + i * 256;          // 0..1023 over 16x64 float4
        int r = f >> 6;                 // 0..15
        int c4 = (f & 63) << 2;         // 0..252 step 4
        *(float4*)&sW[r][c4] = __ldg((const float4*)(W_x + (size_t)(cb * 16 + r) * 256 + c4));
        *(float4*)&sF[r][c4] = *(const float4*)(flow + (size_t)(b0 + r) * 256 + c4);
    }
    __syncthreads();

    // One output per thread: row = tid>>4, local col = tid&15
    {
        int row = tid >> 4;
        int col = tid & 15;
        float s = 0.f;
#pragma unroll 16
        for (int k = 0; k < 256; k += 4) {
            float4 w = *(const float4*)&sW[col][k];
            float4 f = *(const float4*)&sF[row][k];
            s += w.x * f.x + w.y * f.y + w.z * f.z + w.w * f.w;
        }
        int b = b0 + row;
        if (cb == 0)      sdlt[row][col] = s;
        else if (cb == 1) g_Bm[(size_t)b * 16 + col] = s;
        else              g_Cm[(size_t)b * 16 + col] = s;
    }

    if (cb != 0) return;
    __syncthreads();

    // delta: each thread owns channel d = tid, loops over 16 rows
    int d = tid;
    float4 wd0 = __ldg((const float4*)(W_dt + d * 16));
    float4 wd1 = __ldg((const float4*)(W_dt + d * 16 + 4));
    float4 wd2 = __ldg((const float4*)(W_dt + d * 16 + 8));
    float4 wd3 = __ldg((const float4*)(W_dt + d * 16 + 12));
    float bd = __ldg(&b_dt[d]);
#pragma unroll 4
    for (int row = 0; row < 16; row++) {
        const float* dl = &sdlt[row][0];
        float s = bd;
        s += wd0.x * dl[0]  + wd0.y * dl[1]  + wd0.z * dl[2]  + wd0.w * dl[3];
        s += wd1.x * dl[4]  + wd1.y * dl[5]  + wd1.z * dl[6]  + wd1.w * dl[7];
        s += wd2.x * dl[8]  + wd2.y * dl[9]  + wd2.z * dl[10] + wd2.w * dl[11];
        s += wd3.x * dl[12] + wd3.y * dl[13] + wd3.z * dl[14] + wd3.w * dl[15];
        g_delta[(size_t)(b0 + row) * 256 + d] = log1pf(expf(s));
    }
}

// ---------------- K4: SSM state update; one block per row, thread = channel d ----------------
__global__ void __launch_bounds__(256) k_mamba(const float* __restrict__ h,
                                               const float* __restrict__ Dv,
                                               float* __restrict__ h_new) {
    int b = blockIdx.x;
    int d = threadIdx.x;
    __shared__ float sB[16], sC[16];
    if (d < 16)       sB[d] = g_Bm[(size_t)b * 16 + d];
    else if (d < 32)  sC[d - 16] = g_Cm[(size_t)b * 16 + d - 16];
    __syncthreads();

    size_t base = (size_t)b * 256 + d;
    float delta = g_delta[base];
    float u = g_u[base];
    float du = delta * u;
    const float4* hp = (const float4*)(h + base * 16);
    float4* op = (float4*)(h_new + base * 16);
    const float4* ap = (const float4*)(g_negA + d * 16);
    float y = 0.f;
#pragma unroll
    for (int q = 0; q < 4; q++) {
        float4 hv = __ldcs(&hp[q]);
        float4 al = __ldg(&ap[q]);
        float4 o;
        o.x = __expf(al.x * delta) * hv.x + du * sB[q * 4 + 0];
        o.y = __expf(al.y * delta) * hv.y + du * sB[q * 4 + 1];
        o.z = __expf(al.z * delta) * hv.z + du * sB[q * 4 + 2];
        o.w = __expf(al.w * delta) * hv.w + du * sB[q * 4 + 3];
        __stcs(&op[q], o);
        y += o.x * sC[q * 4 + 0] + o.y * sC[q * 4 + 1]
           + o.z * sC[q * 4 + 2] + o.w * sC[q * 4 + 3];
    }
    y += u * __ldg(&Dv[d]);
    float g = g_gate[base];
    g_y[base] = y * siluf(g);
}

// ---------------- K7: LayerNorm + 4-way head + sigmoid; warp per row ----------------
__global__ void __launch_bounds__(256) k_head(const float* __restrict__ gamma,
                                              const float* __restrict__ beta,
                                              const float* __restrict__ W_bb,
                                              const float* __restrict__ b_bb,
                                              float* __restrict__ out) {
    int warp = threadIdx.x >> 5;
    int lane = threadIdx.x & 31;
    int b = blockIdx.x * 8 + warp;
    const float* srow = g_s + (size_t)b * 256;

    float v[8];
    float sum = 0.f;
#pragma unroll
    for (int i = 0; i < 8; i++) { v[i] = srow[i * 32 + lane]; sum += v[i]; }
#pragma unroll
    for (int o = 16; o > 0; o >>= 1) sum += __shfl_xor_sync(0xffffffffu, sum, o);
    float mu = sum * (1.f / 256.f);
    float sq = 0.f;
#pragma unroll
    for (int i = 0; i < 8; i++) { float dd = v[i] - mu; sq += dd * dd; }
#pragma unroll
    for (int o = 16; o > 0; o >>= 1) sq += __shfl_xor_sync(0xffffffffu, sq, o);
    float inv = rsqrtf(sq * (1.f / 256.f) + 1e-5f);

    float a0 = 0.f, a1 = 0.f, a2 = 0.f, a3 = 0.f;
#pragma unroll
    for (int i = 0; i < 8; i++) {
        int c = i * 32 + lane;
        float sn = (v[i] - mu) * inv * __ldg(&gamma[c]) + __ldg(&beta[c]);
        a0 += sn * __ldg(&W_bb[c]);
        a1 += sn * __ldg(&W_bb[256 + c]);
        a2 += sn * __ldg(&W_bb[512 + c]);
        a3 += sn * __ldg(&W_bb[768 + c]);
    }
#pragma unroll
    for (int o = 16; o > 0; o >>= 1) {
        a0 += __shfl_xor_sync(0xffffffffu, a0, o);
        a1 += __shfl_xor_sync(0xffffffffu, a1, o);
        a2 += __shfl_xor_sync(0xffffffffu, a2, o);
        a3 += __shfl_xor_sync(0xffffffffu, a3, o);
    }
    if (lane == 0) {
        out[b * 4 + 0] = 1.f / (1.f + expf(-(a0 + __ldg(&b_bb[0]))));
        out[b * 4 + 1] = 1.f / (1.f + expf(-(a1 + __ldg(&b_bb[1]))));
        out[b * 4 + 2] = 1.f / (1.f + expf(-(a2 + __ldg(&b_bb[2]))));
        out[b * 4 + 3] = 1.f / (1.f + expf(-(a3 + __ldg(&b_bb[3]))));
    }
}

extern "C" void kernel_launch(void* const* d_in, const int* in_sizes, int n_in,
                              void* d_out, int out_size) {
    const float* x0    = (const float*)d_in[0];
    const float* flow  = (const float*)d_in[1];
    const float* h     = (const float*)d_in[2];
    const float* W_in  = (const float*)d_in[3];
    const float* W_x   = (const float*)d_in[4];
    const float* W_dt  = (const float*)d_in[5];
    const float* b_dt  = (const float*)d_in[6];
    const float* A_log = (const float*)d_in[7];
    const float* Dv    = (const float*)d_in[8];
    const float* W1    = (const float*)d_in[9];
    const float* b1    = (const float*)d_in[10];
    const float* W2    = (const float*)d_in[11];
    const float* b2    = (const float*)d_in[12];
    const float* gamma = (const float*)d_in[13];
    const float* beta  = (const float*)d_in[14];
    const float* W_bb  = (const float*)d_in[15];
    const float* b_bb  = (const float*)d_in[16];

    float* out   = (float*)d_out;                 // (B, 4)
    float* h_new = out + (size_t)BTOT * 4;        // (B, 256, 16)

    k_prep<<<16, 256>>>(A_log);
    k_embed<<<BTOT, 256>>>(x0);
    k_sgemm<256, 0><<<dim3(4, BTOT / 128), 256>>>(W_in, (const float*)nullptr);
    k_xdbl<<<dim3(BTOT / 16, 3), 256>>>(flow, W_x, W_dt, b_dt);
    k_mamba<<<BTOT, 256>>>(h, Dv, h_new);
    k_sgemm<256, 1><<<dim3(4, BTOT / 128), 256>>>(W1, b1);
    k_sgemm<512, 2><<<dim3(2, BTOT / 128), 256>>>(W2, b2);
    k_head<<<BTOT / 8, 256>>>(gamma, beta, W_bb, b_bb, out);
}

// round 5
// speedup vs baseline: 1.5120x; 1.2584x over previous
#include <cuda_runtime.h>
#include <cuda_bf16.h>
#include <math.h>
#include <stdint.h>

#define BTOT 32768
#define NDM 256
#define NDI 256
#define NDS 16
#define NFF 512

// ---- scratch (static device globals; no allocation) ----
__device__ float g_u[(size_t)BTOT*NDI];
__device__ float g_gate[(size_t)BTOT*NDI];
__device__ float g_delta[(size_t)BTOT*NDI];
__device__ float g_Bm[(size_t)BTOT*NDS];
__device__ float g_Cm[(size_t)BTOT*NDS];
__device__ float g_y[(size_t)BTOT*NDI];
__device__ float g_s[(size_t)BTOT*NDM];
__device__ float g_negA[NDI*NDS];

// packed split-bf16 activations: row = [hi(0..K-1) | lo(0..K-1)]
__device__ __nv_bfloat16 g_pospk[(size_t)BTOT*512];   // K=256
__device__ __nv_bfloat16 g_ypk[(size_t)BTOT*512];     // K=256
__device__ __nv_bfloat16 g_tpk[(size_t)BTOT*1024];    // K=512
// packed split-bf16 weights: row n = [hi(0..K-1) | lo(0..K-1)]
__device__ __nv_bfloat16 g_W0pk[512*512];
__device__ __nv_bfloat16 g_W1pk[512*512];
__device__ __nv_bfloat16 g_W2pk[256*1024];

__device__ __forceinline__ float siluf(float x) { return x / (1.f + __expf(-x)); }

__device__ __forceinline__ void packsplit(float v, __nv_bfloat16* hi_p, __nv_bfloat16* lo_p) {
    __nv_bfloat16 hi = __float2bfloat16(v);
    *hi_p = hi;
    *lo_p = __float2bfloat16(v - __bfloat162float(hi));
}

// ---------------- K0a: precompute -exp(A_log) ----------------
__global__ void k_prep(const float* __restrict__ A_log) {
    int i = blockIdx.x * 256 + threadIdx.x;
    g_negA[i] = -expf(A_log[i]);
}

// ---------------- K0b: pack weights to split bf16 ----------------
__global__ void k_packw(const float* __restrict__ W, int K, int sel) {
    int i = blockIdx.x * 256 + threadIdx.x;    // over rows*K
    int n = i / K, k = i - n * K;
    __nv_bfloat16* dst = sel == 0 ? g_W0pk : (sel == 1 ? g_W1pk : g_W2pk);
    float v = W[i];
    __nv_bfloat16 hi = __float2bfloat16(v);
    dst[(size_t)n * 2 * K + k] = hi;
    dst[(size_t)n * 2 * K + K + k] = __float2bfloat16(v - __bfloat162float(hi));
}

// ---------------- K1: sine embedding (writes packed bf16 split) ----------------
__global__ void __launch_bounds__(256) k_embed(const float* __restrict__ x0) {
    int idx = blockIdx.x * 256 + threadIdx.x;        // over BTOT*256
    int b = idx >> 8;
    int c = idx & 255;
    int a = c >> 6;
    int w = c & 63;
    int j = w >> 1;
    float v = x0[b * 4 + a];
    float freq_inv = __expf(-(float)j * 0.28782313662425576f); // ln(10000)/32
    float p = v * 6.283185307179586f * freq_inv;
    float val = (w & 1) ? __cosf(p) : __sinf(p);
    packsplit(val, &g_pospk[(size_t)b * 512 + c], &g_pospk[(size_t)b * 512 + 256 + c]);
}

// ================= HMMA (mma.sync bf16) split-bf16 GEMM =================
// C[m,n] = sum_k A[m,k]*W[n,k], via D = Ah*Wh + Ah*Wl + Al*Wh (fp32 regs)
// MODE 0: A=g_pospk K=256, NOUT=512: n<256 -> g_u=silu(v), else g_gate=v
// MODE 1: A=g_ypk   K=256, NOUT=512: g_tpk = packsplit(relu(v + b1[n]))
// MODE 2: A=g_tpk   K=512, NOUT=256: g_s = v + b2[n] + g_y[m,n]

__device__ __forceinline__ void ldsm_x4(uint32_t* a, uint32_t addr) {
    asm volatile("ldmatrix.sync.aligned.m8n8.x4.shared.b16 {%0,%1,%2,%3}, [%4];"
                 : "=r"(a[0]), "=r"(a[1]), "=r"(a[2]), "=r"(a[3]) : "r"(addr));
}
__device__ __forceinline__ void ldsm_x2(uint32_t* b, uint32_t addr) {
    asm volatile("ldmatrix.sync.aligned.m8n8.x2.shared.b16 {%0,%1}, [%2];"
                 : "=r"(b[0]), "=r"(b[1]) : "r"(addr));
}
__device__ __forceinline__ void mma16816(float* d, const uint32_t* a, const uint32_t* b) {
    asm volatile(
        "mma.sync.aligned.m16n8k16.row.col.f32.bf16.bf16.f32 "
        "{%0,%1,%2,%3}, {%4,%5,%6,%7}, {%8,%9}, {%0,%1,%2,%3};"
        : "+f"(d[0]), "+f"(d[1]), "+f"(d[2]), "+f"(d[3])
        : "r"(a[0]), "r"(a[1]), "r"(a[2]), "r"(a[3]), "r"(b[0]), "r"(b[1]));
}

template <int KDIM, int NOUT, int MODE>
__global__ void __launch_bounds__(256) k_hgemm(const float* __restrict__ bias) {
    __shared__ __align__(16) char sA[128 * 128];   // 128 rows x 64 bf16 (swizzled)
    __shared__ __align__(16) char sB[128 * 128];

    const __nv_bfloat16* __restrict__ Apk =
        MODE == 0 ? g_pospk : (MODE == 1 ? g_ypk : g_tpk);
    const __nv_bfloat16* __restrict__ Wpk =
        MODE == 0 ? g_W0pk : (MODE == 1 ? g_W1pk : g_W2pk);

    const int tid = threadIdx.x;
    const int wid = tid >> 5;
    const int lane = tid & 31;
    const int wm = wid & 1;         // 2 m-blocks of 64
    const int wn = wid >> 1;        // 4 n-blocks of 32
    const int m0 = blockIdx.y * 128;
    const int n0 = blockIdx.x * 128;
    const uint32_t sAb = (uint32_t)__cvta_generic_to_shared(sA);
    const uint32_t sBb = (uint32_t)__cvta_generic_to_shared(sB);

    float acc[4][4][4];
#pragma unroll
    for (int i = 0; i < 4; i++)
#pragma unroll
        for (int j = 0; j < 4; j++)
#pragma unroll
            for (int q = 0; q < 4; q++) acc[i][j][q] = 0.f;

#pragma unroll 1
    for (int pass = 0; pass < 3; pass++) {
        const int aoff = (pass == 2) ? KDIM : 0;   // Al on pass 2
        const int boff = (pass == 1) ? KDIM : 0;   // Wl on pass 1
#pragma unroll 1
        for (int kc = 0; kc < KDIM; kc += 64) {
            // stage A/B 128x64 bf16 tiles, XOR-swizzled rows of 128B
#pragma unroll
            for (int i = 0; i < 4; i++) {
                int f = tid + i * 256;          // 0..1023
                int r = f >> 3;                 // row 0..127
                int c16 = f & 7;                // 16B group
                int off = r * 128 + ((c16 ^ (r & 7)) * 16);
                *(uint4*)(sA + off) =
                    *(const uint4*)(Apk + (size_t)(m0 + r) * (2 * KDIM) + aoff + kc + c16 * 8);
                *(uint4*)(sB + off) =
                    __ldg((const uint4*)(Wpk + (size_t)(n0 + r) * (2 * KDIM) + boff + kc + c16 * 8));
            }
            __syncthreads();
#pragma unroll
            for (int ks = 0; ks < 4; ks++) {
                uint32_t afr[4][4], bfr[4][2];
#pragma unroll
                for (int i = 0; i < 4; i++) {
                    int r = wm * 64 + i * 16 + (lane & 15);
                    int c = ks * 2 + (lane >> 4);
                    ldsm_x4(afr[i], sAb + r * 128 + ((c ^ (r & 7)) * 16));
                }
#pragma unroll
                for (int j = 0; j < 4; j++) {
                    int r = wn * 32 + j * 8 + (lane & 7);
                    int c = ks * 2 + ((lane >> 3) & 1);
                    ldsm_x2(bfr[j], sBb + r * 128 + ((c ^ (r & 7)) * 16));
                }
#pragma unroll
                for (int i = 0; i < 4; i++)
#pragma unroll
                    for (int j = 0; j < 4; j++) mma16816(acc[i][j], afr[i], bfr[j]);
            }
            __syncthreads();
        }
    }

    // epilogue: d0=(g,t2), d1=(g,t2+1), d2=(g+8,t2), d3=(g+8,t2+1)
    const int g = lane >> 2;
    const int t2 = (lane & 3) * 2;
#pragma unroll
    for (int i = 0; i < 4; i++) {
#pragma unroll
        for (int j = 0; j < 4; j++) {
#pragma unroll
            for (int h = 0; h < 2; h++) {
                int m = m0 + wm * 64 + i * 16 + g + h * 8;
                int nb = n0 + wn * 32 + j * 8 + t2;
#pragma unroll
                for (int e = 0; e < 2; e++) {
                    int n = nb + e;
                    float v = acc[i][j][h * 2 + e];
                    if (MODE == 0) {
                        if (n < 256) g_u[(size_t)m * 256 + n] = siluf(v);
                        else         g_gate[(size_t)m * 256 + n - 256] = v;
                    } else if (MODE == 1) {
                        float t = fmaxf(v + __ldg(&bias[n]), 0.f);
                        packsplit(t, &g_tpk[(size_t)m * 1024 + n],
                                     &g_tpk[(size_t)m * 1024 + 512 + n]);
                    } else {
                        g_s[(size_t)m * 256 + n] =
                            v + __ldg(&bias[n]) + g_y[(size_t)m * 256 + n];
                    }
                }
            }
        }
    }
}

// ---------------- K3: x_dbl = flow @ W_x^T, col-split across blockIdx.y ----------------
__global__ void __launch_bounds__(256) k_xdbl(const float* __restrict__ flow,
                                              const float* __restrict__ W_x,
                                              const float* __restrict__ W_dt,
                                              const float* __restrict__ b_dt) {
    __shared__ float sW[16][260];
    __shared__ float sF[16][260];
    __shared__ float sdlt[16][17];
    const int b0 = blockIdx.x * 16;
    const int cb = blockIdx.y;
    const int tid = threadIdx.x;

#pragma unroll
    for (int i = 0; i < 4; i++) {
        int f = tid + i * 256;
        int r = f >> 6;
        int c4 = (f & 63) << 2;
        *(float4*)&sW[r][c4] = __ldg((const float4*)(W_x + (size_t)(cb * 16 + r) * 256 + c4));
        *(float4*)&sF[r][c4] = *(const float4*)(flow + (size_t)(b0 + r) * 256 + c4);
    }
    __syncthreads();

    {
        int row = tid >> 4;
        int col = tid & 15;
        float s = 0.f;
#pragma unroll 16
        for (int k = 0; k < 256; k += 4) {
            float4 w = *(const float4*)&sW[col][k];
            float4 f = *(const float4*)&sF[row][k];
            s += w.x * f.x + w.y * f.y + w.z * f.z + w.w * f.w;
        }
        int b = b0 + row;
        if (cb == 0)      sdlt[row][col] = s;
        else if (cb == 1) g_Bm[(size_t)b * 16 + col] = s;
        else              g_Cm[(size_t)b * 16 + col] = s;
    }

    if (cb != 0) return;
    __syncthreads();

    int d = tid;
    float4 wd0 = __ldg((const float4*)(W_dt + d * 16));
    float4 wd1 = __ldg((const float4*)(W_dt + d * 16 + 4));
    float4 wd2 = __ldg((const float4*)(W_dt + d * 16 + 8));
    float4 wd3 = __ldg((const float4*)(W_dt + d * 16 + 12));
    float bd = __ldg(&b_dt[d]);
#pragma unroll 4
    for (int row = 0; row < 16; row++) {
        const float* dl = &sdlt[row][0];
        float s = bd;
        s += wd0.x * dl[0]  + wd0.y * dl[1]  + wd0.z * dl[2]  + wd0.w * dl[3];
        s += wd1.x * dl[4]  + wd1.y * dl[5]  + wd1.z * dl[6]  + wd1.w * dl[7];
        s += wd2.x * dl[8]  + wd2.y * dl[9]  + wd2.z * dl[10] + wd2.w * dl[11];
        s += wd3.x * dl[12] + wd3.y * dl[13] + wd3.z * dl[14] + wd3.w * dl[15];
        g_delta[(size_t)(b0 + row) * 256 + d] = log1pf(expf(s));
    }
}

// ---------------- K4: SSM state update (also writes packed y) ----------------
__global__ void __launch_bounds__(256) k_mamba(const float* __restrict__ h,
                                               const float* __restrict__ Dv,
                                               float* __restrict__ h_new) {
    int b = blockIdx.x;
    int d = threadIdx.x;
    __shared__ float sB[16], sC[16];
    if (d < 16)       sB[d] = g_Bm[(size_t)b * 16 + d];
    else if (d < 32)  sC[d - 16] = g_Cm[(size_t)b * 16 + d - 16];
    __syncthreads();

    size_t base = (size_t)b * 256 + d;
    float delta = g_delta[base];
    float u = g_u[base];
    float du = delta * u;
    const float4* hp = (const float4*)(h + base * 16);
    float4* op = (float4*)(h_new + base * 16);
    const float4* ap = (const float4*)(g_negA + d * 16);
    float y = 0.f;
#pragma unroll
    for (int q = 0; q < 4; q++) {
        float4 hv = __ldcs(&hp[q]);
        float4 al = __ldg(&ap[q]);
        float4 o;
        o.x = __expf(al.x * delta) * hv.x + du * sB[q * 4 + 0];
        o.y = __expf(al.y * delta) * hv.y + du * sB[q * 4 + 1];
        o.z = __expf(al.z * delta) * hv.z + du * sB[q * 4 + 2];
        o.w = __expf(al.w * delta) * hv.w + du * sB[q * 4 + 3];
        __stcs(&op[q], o);
        y += o.x * sC[q * 4 + 0] + o.y * sC[q * 4 + 1]
           + o.z * sC[q * 4 + 2] + o.w * sC[q * 4 + 3];
    }
    y += u * __ldg(&Dv[d]);
    float g = g_gate[base];
    float yv = y * siluf(g);
    g_y[base] = yv;
    packsplit(yv, &g_ypk[(size_t)b * 512 + d], &g_ypk[(size_t)b * 512 + 256 + d]);
}

// ---------------- K7: LayerNorm + 4-way head + sigmoid; warp per row ----------------
__global__ void __launch_bounds__(256) k_head(const float* __restrict__ gamma,
                                              const float* __restrict__ beta,
                                              const float* __restrict__ W_bb,
                                              const float* __restrict__ b_bb,
                                              float* __restrict__ out) {
    int warp = threadIdx.x >> 5;
    int lane = threadIdx.x & 31;
    int b = blockIdx.x * 8 + warp;
    const float* srow = g_s + (size_t)b * 256;

    float v[8];
    float sum = 0.f;
#pragma unroll
    for (int i = 0; i < 8; i++) { v[i] = srow[i * 32 + lane]; sum += v[i]; }
#pragma unroll
    for (int o = 16; o > 0; o >>= 1) sum += __shfl_xor_sync(0xffffffffu, sum, o);
    float mu = sum * (1.f / 256.f);
    float sq = 0.f;
#pragma unroll
    for (int i = 0; i < 8; i++) { float dd = v[i] - mu; sq += dd * dd; }
#pragma unroll
    for (int o = 16; o > 0; o >>= 1) sq += __shfl_xor_sync(0xffffffffu, sq, o);
    float inv = rsqrtf(sq * (1.f / 256.f) + 1e-5f);

    float a0 = 0.f, a1 = 0.f, a2 = 0.f, a3 = 0.f;
#pragma unroll
    for (int i = 0; i < 8; i++) {
        int c = i * 32 + lane;
        float sn = (v[i] - mu) * inv * __ldg(&gamma[c]) + __ldg(&beta[c]);
        a0 += sn * __ldg(&W_bb[c]);
        a1 += sn * __ldg(&W_bb[256 + c]);
        a2 += sn * __ldg(&W_bb[512 + c]);
        a3 += sn * __ldg(&W_bb[768 + c]);
    }
#pragma unroll
    for (int o = 16; o > 0; o >>= 1) {
        a0 += __shfl_xor_sync(0xffffffffu, a0, o);
        a1 += __shfl_xor_sync(0xffffffffu, a1, o);
        a2 += __shfl_xor_sync(0xffffffffu, a2, o);
        a3 += __shfl_xor_sync(0xffffffffu, a3, o);
    }
    if (lane == 0) {
        out[b * 4 + 0] = 1.f / (1.f + expf(-(a0 + __ldg(&b_bb[0]))));
        out[b * 4 + 1] = 1.f / (1.f + expf(-(a1 + __ldg(&b_bb[1]))));
        out[b * 4 + 2] = 1.f / (1.f + expf(-(a2 + __ldg(&b_bb[2]))));
        out[b * 4 + 3] = 1.f / (1.f + expf(-(a3 + __ldg(&b_bb[3]))));
    }
}

extern "C" void kernel_launch(void* const* d_in, const int* in_sizes, int n_in,
                              void* d_out, int out_size) {
    const float* x0    = (const float*)d_in[0];
    const float* flow  = (const float*)d_in[1];
    const float* h     = (const float*)d_in[2];
    const float* W_in  = (const float*)d_in[3];
    const float* W_x   = (const float*)d_in[4];
    const float* W_dt  = (const float*)d_in[5];
    const float* b_dt  = (const float*)d_in[6];
    const float* A_log = (const float*)d_in[7];
    const float* Dv    = (const float*)d_in[8];
    const float* W1    = (const float*)d_in[9];
    const float* b1    = (const float*)d_in[10];
    const float* W2    = (const float*)d_in[11];
    const float* b2    = (const float*)d_in[12];
    const float* gamma = (const float*)d_in[13];
    const float* beta  = (const float*)d_in[14];
    const float* W_bb  = (const float*)d_in[15];
    const float* b_bb  = (const float*)d_in[16];

    float* out   = (float*)d_out;                 // (B, 4)
    float* h_new = out + (size_t)BTOT * 4;        // (B, 256, 16)

    k_prep<<<16, 256>>>(A_log);
    k_packw<<<512, 256>>>(W_in, 256, 0);
    k_packw<<<512, 256>>>(W1, 256, 1);
    k_packw<<<512, 256>>>(W2, 512, 2);
    k_embed<<<BTOT, 256>>>(x0);
    k_hgemm<256, 512, 0><<<dim3(4, BTOT / 128), 256>>>((const float*)nullptr);
    k_xdbl<<<dim3(BTOT / 16, 3), 256>>>(flow, W_x, W_dt, b_dt);
    k_mamba<<<BTOT, 256>>>(h, Dv, h_new);
    k_hgemm<256, 512, 1><<<dim3(4, BTOT / 128), 256>>>(b1);
    k_hgemm<512, 256, 2><<<dim3(2, BTOT / 128), 256>>>(b2);
    k_head<<<BTOT / 8, 256>>>(gamma, beta, W_bb, b_bb, out);
}

// round 6
// speedup vs baseline: 2.0556x; 1.3595x over previous
#include <cuda_runtime.h>
#include <cuda_bf16.h>
#include <math.h>
#include <stdint.h>

#define BTOT 32768
#define NDM 256
#define NDI 256
#define NDS 16
#define NFF 512

// ---- scratch (static device globals; no allocation) ----
__device__ float g_u[(size_t)BTOT*NDI];
__device__ float g_gate[(size_t)BTOT*NDI];
__device__ float g_delta[(size_t)BTOT*NDI];
__device__ float g_Bm[(size_t)BTOT*NDS];
__device__ float g_Cm[(size_t)BTOT*NDS];
__device__ float g_y[(size_t)BTOT*NDI];
__device__ float g_s[(size_t)BTOT*NDM];
__device__ float g_negA[NDI*NDS];

// packed split-bf16 activations: row = [hi(0..K-1) | lo(0..K-1)]
__device__ __nv_bfloat16 g_pospk[(size_t)BTOT*512];   // K=256
__device__ __nv_bfloat16 g_ypk[(size_t)BTOT*512];     // K=256
__device__ __nv_bfloat16 g_tpk[(size_t)BTOT*1024];    // K=512
// packed split-bf16 weights: row n = [hi(0..K-1) | lo(0..K-1)]
__device__ __nv_bfloat16 g_W0pk[512*512];
__device__ __nv_bfloat16 g_W1pk[512*512];
__device__ __nv_bfloat16 g_W2pk[256*1024];

__device__ __forceinline__ float siluf(float x) { return x / (1.f + __expf(-x)); }

__device__ __forceinline__ void packsplit(float v, __nv_bfloat16* hi_p, __nv_bfloat16* lo_p) {
    __nv_bfloat16 hi = __float2bfloat16(v);
    *hi_p = hi;
    *lo_p = __float2bfloat16(v - __bfloat162float(hi));
}

// ---------------- K0a: precompute -exp(A_log) ----------------
__global__ void k_prep(const float* __restrict__ A_log) {
    int i = blockIdx.x * 256 + threadIdx.x;
    g_negA[i] = -expf(A_log[i]);
}

// ---------------- K0b: pack weights to split bf16 ----------------
__global__ void k_packw(const float* __restrict__ W, int K, int sel) {
    int i = blockIdx.x * 256 + threadIdx.x;    // over rows*K
    int n = i / K, k = i - n * K;
    __nv_bfloat16* dst = sel == 0 ? g_W0pk : (sel == 1 ? g_W1pk : g_W2pk);
    float v = W[i];
    __nv_bfloat16 hi = __float2bfloat16(v);
    dst[(size_t)n * 2 * K + k] = hi;
    dst[(size_t)n * 2 * K + K + k] = __float2bfloat16(v - __bfloat162float(hi));
}

// ---------------- K1: sine embedding (writes packed bf16 split) ----------------
__global__ void __launch_bounds__(256) k_embed(const float* __restrict__ x0) {
    int idx = blockIdx.x * 256 + threadIdx.x;        // over BTOT*256
    int b = idx >> 8;
    int c = idx & 255;
    int a = c >> 6;
    int w = c & 63;
    int j = w >> 1;
    float v = x0[b * 4 + a];
    float freq_inv = __expf(-(float)j * 0.28782313662425576f); // ln(10000)/32
    float p = v * 6.283185307179586f * freq_inv;
    float val = (w & 1) ? __cosf(p) : __sinf(p);
    packsplit(val, &g_pospk[(size_t)b * 512 + c], &g_pospk[(size_t)b * 512 + 256 + c]);
}

// ================= HMMA (mma.sync bf16) split-bf16 GEMM, cp.async pipelined =================
// C[m,n] = sum_k A[m,k]*W[n,k], via D = Ah*Wh + Ah*Wl + Al*Wh (fp32 regs)
// MODE 0: A=g_pospk K=256, NOUT=512: n<256 -> g_u=silu(v), else g_gate=v
// MODE 1: A=g_ypk   K=256, NOUT=512: g_tpk = packsplit(relu(v + b1[n]))
// MODE 2: A=g_tpk   K=512, NOUT=256: g_s = v + b2[n] + g_y[m,n]

__device__ __forceinline__ void ldsm_x4(uint32_t* a, uint32_t addr) {
    asm volatile("ldmatrix.sync.aligned.m8n8.x4.shared.b16 {%0,%1,%2,%3}, [%4];"
                 : "=r"(a[0]), "=r"(a[1]), "=r"(a[2]), "=r"(a[3]) : "r"(addr));
}
__device__ __forceinline__ void ldsm_x2(uint32_t* b, uint32_t addr) {
    asm volatile("ldmatrix.sync.aligned.m8n8.x2.shared.b16 {%0,%1}, [%2];"
                 : "=r"(b[0]), "=r"(b[1]) : "r"(addr));
}
__device__ __forceinline__ void mma16816(float* d, const uint32_t* a, const uint32_t* b) {
    asm volatile(
        "mma.sync.aligned.m16n8k16.row.col.f32.bf16.bf16.f32 "
        "{%0,%1,%2,%3}, {%4,%5,%6,%7}, {%8,%9}, {%0,%1,%2,%3};"
        : "+f"(d[0]), "+f"(d[1]), "+f"(d[2]), "+f"(d[3])
        : "r"(a[0]), "r"(a[1]), "r"(a[2]), "r"(a[3]), "r"(b[0]), "r"(b[1]));
}
__device__ __forceinline__ void cp16(uint32_t smem, const void* gmem) {
    asm volatile("cp.async.cg.shared.global [%0], [%1], 16;"
                 :: "r"(smem), "l"(gmem));
}
__device__ __forceinline__ void cp_commit() {
    asm volatile("cp.async.commit_group;");
}
template <int N>
__device__ __forceinline__ void cp_wait() {
    asm volatile("cp.async.wait_group %0;" :: "n"(N));
}

template <int KDIM, int NOUT, int MODE>
__global__ void __launch_bounds__(256) k_hgemm(const float* __restrict__ bias) {
    extern __shared__ char smem_raw[];
    const __nv_bfloat16* __restrict__ Apk =
        MODE == 0 ? g_pospk : (MODE == 1 ? g_ypk : g_tpk);
    const __nv_bfloat16* __restrict__ Wpk =
        MODE == 0 ? g_W0pk : (MODE == 1 ? g_W1pk : g_W2pk);

    constexpr int KD2 = 2 * KDIM;
    constexpr int KCH = KDIM / 64;      // 64-col chunks per pass
    constexpr int NCH = 3 * KCH;        // total chunks over 3 passes
    constexpr int STG = 32768;          // stage size: 16KB A + 16KB B

    const int tid = threadIdx.x;
    const int wid = tid >> 5;
    const int lane = tid & 31;
    const int wm = wid & 1;         // 2 m-blocks of 64
    const int wn = wid >> 1;        // 4 n-blocks of 32
    const int m0 = blockIdx.y * 128;
    const int n0 = blockIdx.x * 128;
    uint32_t sb = (uint32_t)__cvta_generic_to_shared(smem_raw);
    sb = (sb + 127u) & ~127u;

    // per-thread staging coords (4 16B groups per tile)
    const int sr = tid >> 3;            // rows: tid covers 32 rows per step (x4 steps=128)
    const int sc = tid & 7;             // 16B group
    const uint32_t soff = (uint32_t)(((sc ^ (sr & 7)) * 16));

    auto stage = [&](int c, int buf) {
        int pass = c / KCH;
        int kc = (c - pass * KCH) * 64;
        int acol = (pass == 2 ? KDIM : 0) + kc;
        int bcol = (pass == 1 ? KDIM : 0) + kc;
        uint32_t abase = sb + buf * STG;
        uint32_t bbase = abase + 16384;
        const __nv_bfloat16* ag = Apk + (size_t)(m0 + sr) * KD2 + acol + sc * 8;
        const __nv_bfloat16* wg = Wpk + (size_t)(n0 + sr) * KD2 + bcol + sc * 8;
#pragma unroll
        for (int i = 0; i < 4; i++) {
            int r = sr + i * 32;
            cp16(abase + r * 128 + soff, ag + (size_t)i * 32 * KD2);
            cp16(bbase + r * 128 + soff, wg + (size_t)i * 32 * KD2);
        }
    };

    float acc[4][4][4];
#pragma unroll
    for (int i = 0; i < 4; i++)
#pragma unroll
        for (int j = 0; j < 4; j++)
#pragma unroll
            for (int q = 0; q < 4; q++) acc[i][j][q] = 0.f;

    stage(0, 0);
    cp_commit();

#pragma unroll 1
    for (int c = 0; c < NCH; c++) {
        if (c + 1 < NCH) {
            stage(c + 1, (c + 1) & 1);
            cp_commit();
            cp_wait<1>();
        } else {
            cp_wait<0>();
        }
        __syncthreads();
        uint32_t sAb = sb + (c & 1) * STG;
        uint32_t sBb = sAb + 16384;
#pragma unroll
        for (int ks = 0; ks < 4; ks++) {
            uint32_t afr[4][4], bfr[4][2];
#pragma unroll
            for (int i = 0; i < 4; i++) {
                int r = wm * 64 + i * 16 + (lane & 15);
                int cc = ks * 2 + (lane >> 4);
                ldsm_x4(afr[i], sAb + r * 128 + ((cc ^ (r & 7)) * 16));
            }
#pragma unroll
            for (int j = 0; j < 4; j++) {
                int r = wn * 32 + j * 8 + (lane & 7);
                int cc = ks * 2 + ((lane >> 3) & 1);
                ldsm_x2(bfr[j], sBb + r * 128 + ((cc ^ (r & 7)) * 16));
            }
#pragma unroll
            for (int i = 0; i < 4; i++)
#pragma unroll
                for (int j = 0; j < 4; j++) mma16816(acc[i][j], afr[i], bfr[j]);
        }
        __syncthreads();
    }

    // epilogue: d0=(g,t2), d1=(g,t2+1), d2=(g+8,t2), d3=(g+8,t2+1)
    const int g = lane >> 2;
    const int t2 = (lane & 3) * 2;
#pragma unroll
    for (int i = 0; i < 4; i++) {
#pragma unroll
        for (int j = 0; j < 4; j++) {
#pragma unroll
            for (int h = 0; h < 2; h++) {
                int m = m0 + wm * 64 + i * 16 + g + h * 8;
                int nb = n0 + wn * 32 + j * 8 + t2;
#pragma unroll
                for (int e = 0; e < 2; e++) {
                    int n = nb + e;
                    float v = acc[i][j][h * 2 + e];
                    if (MODE == 0) {
                        if (n < 256) g_u[(size_t)m * 256 + n] = siluf(v);
                        else         g_gate[(size_t)m * 256 + n - 256] = v;
                    } else if (MODE == 1) {
                        float t = fmaxf(v + __ldg(&bias[n]), 0.f);
                        packsplit(t, &g_tpk[(size_t)m * 1024 + n],
                                     &g_tpk[(size_t)m * 1024 + 512 + n]);
                    } else {
                        g_s[(size_t)m * 256 + n] =
                            v + __ldg(&bias[n]) + g_y[(size_t)m * 256 + n];
                    }
                }
            }
        }
    }
}

// ---------------- K3: x_dbl = flow @ W_x^T, col-split across blockIdx.y ----------------
__global__ void __launch_bounds__(256) k_xdbl(const float* __restrict__ flow,
                                              const float* __restrict__ W_x,
                                              const float* __restrict__ W_dt,
                                              const float* __restrict__ b_dt) {
    __shared__ float sW[16][260];
    __shared__ float sF[16][260];
    __shared__ float sdlt[16][17];
    const int b0 = blockIdx.x * 16;
    const int cb = blockIdx.y;
    const int tid = threadIdx.x;

#pragma unroll
    for (int i = 0; i < 4; i++) {
        int f = tid + i * 256;
        int r = f >> 6;
        int c4 = (f & 63) << 2;
        *(float4*)&sW[r][c4] = __ldg((const float4*)(W_x + (size_t)(cb * 16 + r) * 256 + c4));
        *(float4*)&sF[r][c4] = *(const float4*)(flow + (size_t)(b0 + r) * 256 + c4);
    }
    __syncthreads();

    {
        int row = tid >> 4;
        int col = tid & 15;
        float s = 0.f;
#pragma unroll 16
        for (int k = 0; k < 256; k += 4) {
            float4 w = *(const float4*)&sW[col][k];
            float4 f = *(const float4*)&sF[row][k];
            s += w.x * f.x + w.y * f.y + w.z * f.z + w.w * f.w;
        }
        int b = b0 + row;
        if (cb == 0)      sdlt[row][col] = s;
        else if (cb == 1) g_Bm[(size_t)b * 16 + col] = s;
        else              g_Cm[(size_t)b * 16 + col] = s;
    }

    if (cb != 0) return;
    __syncthreads();

    int d = tid;
    float4 wd0 = __ldg((const float4*)(W_dt + d * 16));
    float4 wd1 = __ldg((const float4*)(W_dt + d * 16 + 4));
    float4 wd2 = __ldg((const float4*)(W_dt + d * 16 + 8));
    float4 wd3 = __ldg((const float4*)(W_dt + d * 16 + 12));
    float bd = __ldg(&b_dt[d]);
#pragma unroll 4
    for (int row = 0; row < 16; row++) {
        const float* dl = &sdlt[row][0];
        float s = bd;
        s += wd0.x * dl[0]  + wd0.y * dl[1]  + wd0.z * dl[2]  + wd0.w * dl[3];
        s += wd1.x * dl[4]  + wd1.y * dl[5]  + wd1.z * dl[6]  + wd1.w * dl[7];
        s += wd2.x * dl[8]  + wd2.y * dl[9]  + wd2.z * dl[10] + wd2.w * dl[11];
        s += wd3.x * dl[12] + wd3.y * dl[13] + wd3.z * dl[14] + wd3.w * dl[15];
        g_delta[(size_t)(b0 + row) * 256 + d] = log1pf(expf(s));
    }
}

// ---------------- K4: SSM state update (also writes packed y) ----------------
__global__ void __launch_bounds__(256) k_mamba(const float* __restrict__ h,
                                               const float* __restrict__ Dv,
                                               float* __restrict__ h_new) {
    int b = blockIdx.x;
    int d = threadIdx.x;
    __shared__ float sB[16], sC[16];
    if (d < 16)       sB[d] = g_Bm[(size_t)b * 16 + d];
    else if (d < 32)  sC[d - 16] = g_Cm[(size_t)b * 16 + d - 16];
    __syncthreads();

    size_t base = (size_t)b * 256 + d;
    float delta = g_delta[base];
    float u = g_u[base];
    float du = delta * u;
    const float4* hp = (const float4*)(h + base * 16);
    float4* op = (float4*)(h_new + base * 16);
    const float4* ap = (const float4*)(g_negA + d * 16);
    float y = 0.f;
#pragma unroll
    for (int q = 0; q < 4; q++) {
        float4 hv = __ldcs(&hp[q]);
        float4 al = __ldg(&ap[q]);
        float4 o;
        o.x = __expf(al.x * delta) * hv.x + du * sB[q * 4 + 0];
        o.y = __expf(al.y * delta) * hv.y + du * sB[q * 4 + 1];
        o.z = __expf(al.z * delta) * hv.z + du * sB[q * 4 + 2];
        o.w = __expf(al.w * delta) * hv.w + du * sB[q * 4 + 3];
        __stcs(&op[q], o);
        y += o.x * sC[q * 4 + 0] + o.y * sC[q * 4 + 1]
           + o.z * sC[q * 4 + 2] + o.w * sC[q * 4 + 3];
    }
    y += u * __ldg(&Dv[d]);
    float g = g_gate[base];
    float yv = y * siluf(g);
    g_y[base] = yv;
    packsplit(yv, &g_ypk[(size_t)b * 512 + d], &g_ypk[(size_t)b * 512 + 256 + d]);
}

// ---------------- K7: LayerNorm + 4-way head + sigmoid; warp per row ----------------
__global__ void __launch_bounds__(256) k_head(const float* __restrict__ gamma,
                                              const float* __restrict__ beta,
                                              const float* __restrict__ W_bb,
                                              const float* __restrict__ b_bb,
                                              float* __restrict__ out) {
    int warp = threadIdx.x >> 5;
    int lane = threadIdx.x & 31;
    int b = blockIdx.x * 8 + warp;
    const float* srow = g_s + (size_t)b * 256;

    float v[8];
    float sum = 0.f;
#pragma unroll
    for (int i = 0; i < 8; i++) { v[i] = srow[i * 32 + lane]; sum += v[i]; }
#pragma unroll
    for (int o = 16; o > 0; o >>= 1) sum += __shfl_xor_sync(0xffffffffu, sum, o);
    float mu = sum * (1.f / 256.f);
    float sq = 0.f;
#pragma unroll
    for (int i = 0; i < 8; i++) { float dd = v[i] - mu; sq += dd * dd; }
#pragma unroll
    for (int o = 16; o > 0; o >>= 1) sq += __shfl_xor_sync(0xffffffffu, sq, o);
    float inv = rsqrtf(sq * (1.f / 256.f) + 1e-5f);

    float a0 = 0.f, a1 = 0.f, a2 = 0.f, a3 = 0.f;
#pragma unroll
    for (int i = 0; i < 8; i++) {
        int c = i * 32 + lane;
        float sn = (v[i] - mu) * inv * __ldg(&gamma[c]) + __ldg(&beta[c]);
        a0 += sn * __ldg(&W_bb[c]);
        a1 += sn * __ldg(&W_bb[256 + c]);
        a2 += sn * __ldg(&W_bb[512 + c]);
        a3 += sn * __ldg(&W_bb[768 + c]);
    }
#pragma unroll
    for (int o = 16; o > 0; o >>= 1) {
        a0 += __shfl_xor_sync(0xffffffffu, a0, o);
        a1 += __shfl_xor_sync(0xffffffffu, a1, o);
        a2 += __shfl_xor_sync(0xffffffffu, a2, o);
        a3 += __shfl_xor_sync(0xffffffffu, a3, o);
    }
    if (lane == 0) {
        out[b * 4 + 0] = 1.f / (1.f + expf(-(a0 + __ldg(&b_bb[0]))));
        out[b * 4 + 1] = 1.f / (1.f + expf(-(a1 + __ldg(&b_bb[1]))));
        out[b * 4 + 2] = 1.f / (1.f + expf(-(a2 + __ldg(&b_bb[2]))));
        out[b * 4 + 3] = 1.f / (1.f + expf(-(a3 + __ldg(&b_bb[3]))));
    }
}

extern "C" void kernel_launch(void* const* d_in, const int* in_sizes, int n_in,
                              void* d_out, int out_size) {
    const float* x0    = (const float*)d_in[0];
    const float* flow  = (const float*)d_in[1];
    const float* h     = (const float*)d_in[2];
    const float* W_in  = (const float*)d_in[3];
    const float* W_x   = (const float*)d_in[4];
    const float* W_dt  = (const float*)d_in[5];
    const float* b_dt  = (const float*)d_in[6];
    const float* A_log = (const float*)d_in[7];
    const float* Dv    = (const float*)d_in[8];
    const float* W1    = (const float*)d_in[9];
    const float* b1    = (const float*)d_in[10];
    const float* W2    = (const float*)d_in[11];
    const float* b2    = (const float*)d_in[12];
    const float* gamma = (const float*)d_in[13];
    const float* beta  = (const float*)d_in[14];
    const float* W_bb  = (const float*)d_in[15];
    const float* b_bb  = (const float*)d_in[16];

    float* out   = (float*)d_out;                 // (B, 4)
    float* h_new = out + (size_t)BTOT * 4;        // (B, 256, 16)

    const int GSMEM = 2 * 32768 + 128;            // 2 stages + align pad
    cudaFuncSetAttribute(k_hgemm<256, 512, 0>,
                         cudaFuncAttributeMaxDynamicSharedMemorySize, GSMEM);
    cudaFuncSetAttribute(k_hgemm<256, 512, 1>,
                         cudaFuncAttributeMaxDynamicSharedMemorySize, GSMEM);
    cudaFuncSetAttribute(k_hgemm<512, 256, 2>,
                         cudaFuncAttributeMaxDynamicSharedMemorySize, GSMEM);

    k_prep<<<16, 256>>>(A_log);
    k_packw<<<512, 256>>>(W_in, 256, 0);
    k_packw<<<512, 256>>>(W1, 256, 1);
    k_packw<<<512, 256>>>(W2, 512, 2);
    k_embed<<<BTOT, 256>>>(x0);
    k_hgemm<256, 512, 0><<<dim3(4, BTOT / 128), 256, GSMEM>>>((const float*)nullptr);
    k_xdbl<<<dim3(BTOT / 16, 3), 256>>>(flow, W_x, W_dt, b_dt);
    k_mamba<<<BTOT, 256>>>(h, Dv, h_new);
    k_hgemm<256, 512, 1><<<dim3(4, BTOT / 128), 256, GSMEM>>>(b1);
    k_hgemm<512, 256, 2><<<dim3(2, BTOT / 128), 256, GSMEM>>>(b2);
    k_head<<<BTOT / 8, 256>>>(gamma, beta, W_bb, b_bb, out);
}